// round 14
// baseline (speedup 1.0000x reference)
#include <cuda_runtime.h>
#include <cuda_bf16.h>
#include <math.h>

typedef unsigned long long ull;

// Problem constants
#define BB   256          // batch
#define TT   512          // seq len
#define HH   256          // hidden
#define GG   1024         // 4*H gates
#define CC   128          // classes
#define MM   (BB*TT)      // 131072 rows for input GEMM

#define SA_STRIDE 264     // sAs row stride (floats): 2r-mod-32 bank pattern

// ---------------- scratch (device globals; no allocs allowed) ----------------
__device__ float g_GX [(size_t)MM * GG];     // 512 MB layer-0 pregates [b][t][gate]
__device__ float g_GX1[(size_t)MM * GG];     // 512 MB layer-1 pregates [b][t][gate]
__device__ float g_H0[BB * HH];
__device__ float g_H1[BB * HH];
__device__ unsigned int g_bars[2][8 * 32];   // per-layer, per-row-group counters

// ---------------- packed f32x2 helpers (Blackwell FFMA2 path) ----------------
__device__ __forceinline__ ull pack2(float x, float y) {
    ull r;
    asm("mov.b64 %0, {%1, %2};" : "=l"(r) : "f"(x), "f"(y));
    return r;
}
__device__ __forceinline__ float2 unpack2(ull v) {
    float2 r;
    asm("mov.b64 {%0, %1}, %2;" : "=f"(r.x), "=f"(r.y) : "l"(v));
    return r;
}
__device__ __forceinline__ ull ffma2x(ull a, ull b, ull c) {
    ull d;
    asm("fma.rn.f32x2 %0, %1, %2, %3;" : "=l"(d) : "l"(a), "l"(b), "l"(c));
    return d;
}

// fast activations (error ~1e-6, well inside 1e-3 budget)
__device__ __forceinline__ float fsigm(float x) {
    float e = __expf(-x);
    return __fdividef(1.0f, 1.0f + e);
}
__device__ __forceinline__ float ftanh(float x) {
    float e = __expf(2.0f * x);           // overflow -> inf -> result 1 (correct)
    return 1.0f - __fdividef(2.0f, e + 1.0f);
}

__device__ __forceinline__ unsigned int ld_acquire_u(const unsigned int* p) {
    unsigned int v;
    asm volatile("ld.global.acquire.gpu.u32 %0, [%1];" : "=r"(v) : "l"(p) : "memory");
    return v;
}

// ---------------- big GEMM (layer-0 pregates only) ----------------------------
// g_GX[m,n] = sum_k x[m,k]*W[n,k] + b1[n] + b2[n].  EXACT R10 structure
// (measured best 1.45ms, fma 59%), plus folded reset of BOTH layers' flags.
__global__ void __launch_bounds__(256) gemm_gx(const float* __restrict__ A,
                                               const float* __restrict__ W,
                                               const float* __restrict__ b1,
                                               const float* __restrict__ b2) {
    __shared__ __align__(16) float As[2][16][128];
    __shared__ __align__(16) float Bs[2][16][64];

    const int tid = threadIdx.x;

    if (blockIdx.x == 0 && blockIdx.y == 0) {
        g_bars[0][tid] = 0u;
        g_bars[1][tid] = 0u;
    }

    float* __restrict__ Cout = g_GX;

    const int ty = tid >> 4;          // 0..15  (m group of 8)
    const int tx = tid & 15;          // 0..15  (n group of 4)
    const int bm0 = blockIdx.y * 128;
    const int bn0 = blockIdx.x * 64;

    const int a_row0 = tid >> 2;              // 0..63
    const int a_kg   = (tid & 3) * 4;
    const int b_row  = tid >> 2;
    const int b_kg   = (tid & 3) * 4;

    ull acc[4][4];
    #pragma unroll
    for (int i = 0; i < 4; i++)
        #pragma unroll
        for (int j = 0; j < 4; j++) acc[i][j] = 0ull;

    {
        #pragma unroll
        for (int i = 0; i < 2; i++) {
            int row = a_row0 + i * 64;
            float4 v = *(const float4*)&A[(size_t)(bm0 + row) * 256 + a_kg];
            As[0][a_kg + 0][row] = v.x; As[0][a_kg + 1][row] = v.y;
            As[0][a_kg + 2][row] = v.z; As[0][a_kg + 3][row] = v.w;
        }
        float4 v = *(const float4*)&W[(size_t)(bn0 + b_row) * 256 + b_kg];
        Bs[0][b_kg + 0][b_row] = v.x; Bs[0][b_kg + 1][b_row] = v.y;
        Bs[0][b_kg + 2][b_row] = v.z; Bs[0][b_kg + 3][b_row] = v.w;
    }
    __syncthreads();

    int buf = 0;
    for (int k0 = 0; k0 < 256; k0 += 16) {
        float4 pa0, pa1, pb;
        const bool more = (k0 + 16) < 256;
        if (more) {
            pa0 = *(const float4*)&A[(size_t)(bm0 + a_row0) * 256 + k0 + 16 + a_kg];
            pa1 = *(const float4*)&A[(size_t)(bm0 + a_row0 + 64) * 256 + k0 + 16 + a_kg];
            pb  = *(const float4*)&W[(size_t)(bn0 + b_row) * 256 + k0 + 16 + b_kg];
        }

        #pragma unroll
        for (int k = 0; k < 16; k++) {
            const ull* ap = (const ull*)&As[buf][k][ty * 8];
            ull a0 = ap[0], a1 = ap[1], a2 = ap[2], a3 = ap[3];
            float4 bv = *(const float4*)&Bs[buf][k][tx * 4];
            ull bb0 = pack2(bv.x, bv.x);
            ull bb1 = pack2(bv.y, bv.y);
            ull bb2 = pack2(bv.z, bv.z);
            ull bb3 = pack2(bv.w, bv.w);
            acc[0][0] = ffma2x(a0, bb0, acc[0][0]);
            acc[1][0] = ffma2x(a1, bb0, acc[1][0]);
            acc[2][0] = ffma2x(a2, bb0, acc[2][0]);
            acc[3][0] = ffma2x(a3, bb0, acc[3][0]);
            acc[0][1] = ffma2x(a0, bb1, acc[0][1]);
            acc[1][1] = ffma2x(a1, bb1, acc[1][1]);
            acc[2][1] = ffma2x(a2, bb1, acc[2][1]);
            acc[3][1] = ffma2x(a3, bb1, acc[3][1]);
            acc[0][2] = ffma2x(a0, bb2, acc[0][2]);
            acc[1][2] = ffma2x(a1, bb2, acc[1][2]);
            acc[2][2] = ffma2x(a2, bb2, acc[2][2]);
            acc[3][2] = ffma2x(a3, bb2, acc[3][2]);
            acc[0][3] = ffma2x(a0, bb3, acc[0][3]);
            acc[1][3] = ffma2x(a1, bb3, acc[1][3]);
            acc[2][3] = ffma2x(a2, bb3, acc[2][3]);
            acc[3][3] = ffma2x(a3, bb3, acc[3][3]);
        }

        if (more) {
            int nb = buf ^ 1;
            As[nb][a_kg + 0][a_row0] = pa0.x; As[nb][a_kg + 1][a_row0] = pa0.y;
            As[nb][a_kg + 2][a_row0] = pa0.z; As[nb][a_kg + 3][a_row0] = pa0.w;
            As[nb][a_kg + 0][a_row0 + 64] = pa1.x; As[nb][a_kg + 1][a_row0 + 64] = pa1.y;
            As[nb][a_kg + 2][a_row0 + 64] = pa1.z; As[nb][a_kg + 3][a_row0 + 64] = pa1.w;
            Bs[nb][b_kg + 0][b_row] = pb.x; Bs[nb][b_kg + 1][b_row] = pb.y;
            Bs[nb][b_kg + 2][b_row] = pb.z; Bs[nb][b_kg + 3][b_row] = pb.w;
            __syncthreads();
            buf = nb;
        }
    }

    float4 b1v = *(const float4*)&b1[bn0 + tx * 4];
    float4 b2v = *(const float4*)&b2[bn0 + tx * 4];
    float4 bias = make_float4(b1v.x + b2v.x, b1v.y + b2v.y,
                              b1v.z + b2v.z, b1v.w + b2v.w);
    #pragma unroll
    for (int i = 0; i < 4; i++) {
        float2 q0 = unpack2(acc[i][0]);
        float2 q1 = unpack2(acc[i][1]);
        float2 q2 = unpack2(acc[i][2]);
        float2 q3 = unpack2(acc[i][3]);
        size_t r0 = (size_t)(bm0 + ty * 8 + 2 * i);
        float4 v0 = make_float4(q0.x + bias.x, q1.x + bias.y, q2.x + bias.z, q3.x + bias.w);
        float4 v1 = make_float4(q0.y + bias.x, q1.y + bias.y, q2.y + bias.z, q3.y + bias.w);
        *(float4*)&Cout[r0 * GG + bn0 + tx * 4] = v0;
        *(float4*)&Cout[(r0 + 1) * GG + bn0 + tx * 4] = v1;
    }
}

// ---------------- persistent recurrence (+ fused next-layer input GEMM) ------
// 128 CTAs x 256 threads. CTA = 32 rows x 16 cols.  DISJOINT-COLUMN mapping:
// warp w owns cols {2w, 2w+1}; thread = (col = 2w+(lane&1), rows rg & rg+16).
// -> each warp reads only ITS weight bytes (32B/LDS.128, no cross-warp
// redundancy); h tile row-major stride 264 puts the 16 row-addresses of each
// h-load on a uniform 2-per-bank pattern (2-wavefront floor).
// Layer 0 additionally computes gx1[t-1] = h0[t-1] @ Wih1^T + biases (fused
// layer-1 input GEMM), with a tail phase for gx1[511].
__global__ void __launch_bounds__(256, 1) lstm_persist(const float* __restrict__ whh,
                                                       const float* __restrict__ wih,
                                                       const float* __restrict__ bi1,
                                                       const float* __restrict__ bh1,
                                                       int layer) {
    extern __shared__ float sm[];
    float* sWs = sm;                 // [256][64]  Whh slice  [k][cl*4+g]
    float* sWi = sm + 256 * 64;      // [256][64]  Wih1 slice [k][cl*4+g]
    float* sAs = sm + 2 * 256 * 64;  // [32][SA_STRIDE] h row-major

    const int hasWih = (layer == 0);
    const float* __restrict__ gxin = hasWih ? g_GX : g_GX1;

    const int tid  = threadIdx.x;
    const int bid  = blockIdx.x;
    const int w    = tid >> 5;                // warp 0..7
    const int lane = tid & 31;
    const int cl   = 2 * w + (lane & 1);      // CTA-local col 0..15
    const int rg   = lane >> 1;               // row group 0..15
    const int c0   = (bid & 15) * 16;         // h-col group
    const int grp  = bid >> 4;                // row group 0..7
    const int bm   = grp * 32;                // batch rows
    const int col  = c0 + cl;

    // one-time weight stage: 64 gate-rows (cl*4+g) x 256 k
    for (int i = tid; i < 64 * 64; i += 256) {
        int lr = i >> 6;              // 0..63 local row (cl*4+g)
        int kk = (i & 63) * 4;        // k0
        int bh = lr >> 2, g = lr & 3;
        float4 v = *(const float4*)&whh[(size_t)(g * HH + c0 + bh) * HH + kk];
        sWs[(kk + 0) * 64 + lr] = v.x;
        sWs[(kk + 1) * 64 + lr] = v.y;
        sWs[(kk + 2) * 64 + lr] = v.z;
        sWs[(kk + 3) * 64 + lr] = v.w;
        if (hasWih) {
            float4 u = *(const float4*)&wih[(size_t)(g * HH + c0 + bh) * HH + kk];
            sWi[(kk + 0) * 64 + lr] = u.x;
            sWi[(kk + 1) * 64 + lr] = u.y;
            sWi[(kk + 2) * 64 + lr] = u.z;
            sWi[(kk + 3) * 64 + lr] = u.w;
        }
    }
    __syncthreads();

    // next-layer biases for this thread's column (layer 0 only)
    float nb_i = 0.f, nb_f = 0.f, nb_g = 0.f, nb_o = 0.f;
    if (hasWih) {
        nb_i = bi1[col]       + bh1[col];
        nb_f = bi1[256 + col] + bh1[256 + col];
        nb_g = bi1[512 + col] + bh1[512 + col];
        nb_o = bi1[768 + col] + bh1[768 + col];
    }

    float creg[2] = {0.f, 0.f};
    int rows[2];
    rows[0] = bm + rg;
    rows[1] = bm + rg + 16;

    // t=0 pregate prefetch
    float pg_i[2], pg_f[2], pg_g[2], pg_o[2];
    #pragma unroll
    for (int r = 0; r < 2; r++) {
        size_t base = (size_t)rows[r] * TT * GG + col;   // t=0
        pg_i[r] = gxin[base];
        pg_f[r] = gxin[base + 256];
        pg_g[r] = gxin[base + 512];
        pg_o[r] = gxin[base + 768];
    }

    const int sr  = tid & 31;          // staging row 0..31
    const int skc = tid >> 5;          // staging k-chunk 0..7 (32 floats each)

    unsigned int* barp = &g_bars[layer][grp * 32];

    const int tEnd = hasWih ? TT : (TT - 1);   // layer 0 runs a tail phase

    for (int t = 0; t <= tEnd; t++) {
        const float* __restrict__ hin  = (t & 1) ? g_H1 : g_H0;
        float* __restrict__       hout = (t & 1) ? g_H0 : g_H1;

        ull aif[2] = {0, 0};     // recurrent (i,f),(g,o)
        ull ago[2] = {0, 0};
        ull bif[2] = {0, 0};     // next-layer input (i,f),(g,o)
        ull bgo[2] = {0, 0};

        if (t > 0) {
            // stage hin (32 rows x 256 k) row-major, vectorized
            {
                const float* hrow = &hin[(bm + sr) * HH + skc * 32];
                float* dst = &sAs[sr * SA_STRIDE + skc * 32];
                #pragma unroll
                for (int j = 0; j < 8; j++)
                    *(float4*)&dst[j * 4] = *(const float4*)&hrow[j * 4];
            }
            __syncthreads();

            const float* hrA = &sAs[(size_t)rows[0] % 32 * 0 + rg * SA_STRIDE];
            const float* hrB = &sAs[(rg + 16) * SA_STRIDE];
            const float* bpW = &sWs[cl * 4];
            const float* bpI = &sWi[cl * 4];

            if (hasWih) {
                #pragma unroll 4
                for (int k4 = 0; k4 < 256; k4 += 4) {
                    float ha[4], hb[4];
                    *(float4*)ha = *(const float4*)&hrA[k4];
                    *(float4*)hb = *(const float4*)&hrB[k4];
                    #pragma unroll
                    for (int j = 0; j < 4; j++) {
                        ulonglong2 wv = *(const ulonglong2*)(bpW + (k4 + j) * 64);
                        ulonglong2 wi = *(const ulonglong2*)(bpI + (k4 + j) * 64);
                        ull a0 = pack2(ha[j], ha[j]);
                        ull a1 = pack2(hb[j], hb[j]);
                        aif[0] = ffma2x(a0, wv.x, aif[0]);
                        ago[0] = ffma2x(a0, wv.y, ago[0]);
                        bif[0] = ffma2x(a0, wi.x, bif[0]);
                        bgo[0] = ffma2x(a0, wi.y, bgo[0]);
                        aif[1] = ffma2x(a1, wv.x, aif[1]);
                        ago[1] = ffma2x(a1, wv.y, ago[1]);
                        bif[1] = ffma2x(a1, wi.x, bif[1]);
                        bgo[1] = ffma2x(a1, wi.y, bgo[1]);
                    }
                }
            } else {
                #pragma unroll 4
                for (int k4 = 0; k4 < 256; k4 += 4) {
                    float ha[4], hb[4];
                    *(float4*)ha = *(const float4*)&hrA[k4];
                    *(float4*)hb = *(const float4*)&hrB[k4];
                    #pragma unroll
                    for (int j = 0; j < 4; j++) {
                        ulonglong2 wv = *(const ulonglong2*)(bpW + (k4 + j) * 64);
                        ull a0 = pack2(ha[j], ha[j]);
                        ull a1 = pack2(hb[j], hb[j]);
                        aif[0] = ffma2x(a0, wv.x, aif[0]);
                        ago[0] = ffma2x(a0, wv.y, ago[0]);
                        aif[1] = ffma2x(a1, wv.x, aif[1]);
                        ago[1] = ffma2x(a1, wv.y, ago[1]);
                    }
                }
            }

            // store next-layer pregates gx1[t-1] (layer 0 only)
            if (hasWih) {
                #pragma unroll
                for (int r = 0; r < 2; r++) {
                    float2 fif = unpack2(bif[r]);
                    float2 fgo = unpack2(bgo[r]);
                    size_t base = ((size_t)rows[r] * TT + (t - 1)) * GG + col;
                    g_GX1[base]       = fif.x + nb_i;
                    g_GX1[base + 256] = fif.y + nb_f;
                    g_GX1[base + 512] = fgo.x + nb_g;
                    g_GX1[base + 768] = fgo.y + nb_o;
                }
            }
        }

        if (t < TT) {
            #pragma unroll
            for (int r = 0; r < 2; r++) {
                float2 fif = unpack2(aif[r]);
                float2 fgo = unpack2(ago[r]);
                float si = fsigm(fif.x + pg_i[r]);
                float sf = fsigm(fif.y + pg_f[r]);
                float tg = ftanh(fgo.x + pg_g[r]);
                float so = fsigm(fgo.y + pg_o[r]);
                float c  = sf * creg[r] + si * tg;
                creg[r]  = c;
                float h  = so * ftanh(c);
                hout[rows[r] * HH + col] = h;
            }
        }

        // ---- per-row-group barrier (16 CTAs per counter) ----
        if (t < tEnd) {
            __syncthreads();                       // sAs reads + h stores done
            if (tid == 0) {
                __threadfence();                   // release h to GPU scope
                atomicAdd(barp, 1u);
            }
            // prefetch next step's pregates into registers while peers arrive
            if (t + 1 < TT) {
                #pragma unroll
                for (int r = 0; r < 2; r++) {
                    size_t base = ((size_t)rows[r] * TT + (t + 1)) * GG + col;
                    pg_i[r] = gxin[base];
                    pg_f[r] = gxin[base + 256];
                    pg_g[r] = gxin[base + 512];
                    pg_o[r] = gxin[base + 768];
                }
            }
            if (tid == 0) {
                unsigned target = (unsigned)(t + 1) * 16u;
                while (ld_acquire_u(barp) < target) { }
            }
            __syncthreads();
        }
    }
}

// ---------------- FC + log_softmax ------------------------------------------
__global__ void __launch_bounds__(128) fc_kernel(const float* __restrict__ wfc,
                                                 const float* __restrict__ bfc,
                                                 float* __restrict__ out) {
    const int b = blockIdx.x;
    const int tid = threadIdx.x;  // 128 = one class per thread
    __shared__ float h[256];
    // t = TT-1 = 511 (odd) -> final hout = g_H0
    h[tid] = g_H0[b * HH + tid];
    h[tid + 128] = g_H0[b * HH + tid + 128];
    __syncthreads();

    float acc = bfc[tid];
    const float* wp = wfc + (size_t)tid * HH;
    #pragma unroll 8
    for (int k = 0; k < 256; k++) acc += h[k] * wp[k];

    float m = acc;
    #pragma unroll
    for (int o = 16; o > 0; o >>= 1)
        m = fmaxf(m, __shfl_xor_sync(0xffffffffu, m, o));
    __shared__ float smax[4], ssum[4];
    int wid = tid >> 5, lane = tid & 31;
    if (lane == 0) smax[wid] = m;
    __syncthreads();
    m = fmaxf(fmaxf(smax[0], smax[1]), fmaxf(smax[2], smax[3]));

    float e = expf(acc - m);
    float s = e;
    #pragma unroll
    for (int o = 16; o > 0; o >>= 1)
        s += __shfl_xor_sync(0xffffffffu, s, o);
    if (lane == 0) ssum[wid] = s;
    __syncthreads();
    s = ssum[0] + ssum[1] + ssum[2] + ssum[3];

    out[b * CC + tid] = acc - m - logf(s);
}

// ---------------- launch ------------------------------------------------------
extern "C" void kernel_launch(void* const* d_in, const int* in_sizes, int n_in,
                              void* d_out, int out_size) {
    const float* x    = (const float*)d_in[0];
    const float* wih0 = (const float*)d_in[1];
    const float* whh0 = (const float*)d_in[2];
    const float* bih0 = (const float*)d_in[3];
    const float* bhh0 = (const float*)d_in[4];
    const float* wih1 = (const float*)d_in[5];
    const float* whh1 = (const float*)d_in[6];
    const float* bih1 = (const float*)d_in[7];
    const float* bhh1 = (const float*)d_in[8];
    const float* wfc  = (const float*)d_in[9];
    const float* bfc  = (const float*)d_in[10];
    float* out = (float*)d_out;

    const int persist_smem = (2 * 256 * 64 + 32 * SA_STRIDE) * (int)sizeof(float); // ~161 KB
    cudaFuncSetAttribute(lstm_persist,
                         cudaFuncAttributeMaxDynamicSharedMemorySize,
                         persist_smem);

    dim3 gemm_grid(16, 1024);   // N/64, M/128

    // 4 launches total: gemm0 -> persist(L0, fused gx1) -> persist(L1) -> fc
    gemm_gx<<<gemm_grid, 256>>>(x, wih0, bih0, bhh0);
    lstm_persist<<<128, 256, persist_smem>>>(whh0, wih1, bih1, bhh1, 0);
    lstm_persist<<<128, 256, persist_smem>>>(whh1, nullptr, nullptr, nullptr, 1);
    fc_kernel<<<256, 128>>>(wfc, bfc, out);
}

// round 15
// speedup vs baseline: 1.1594x; 1.1594x over previous
#include <cuda_runtime.h>
#include <cuda_bf16.h>
#include <math.h>

typedef unsigned long long ull;

// Problem constants
#define BB   256          // batch
#define TT   512          // seq len
#define HH   256          // hidden
#define GG   1024         // 4*H gates
#define CC   128          // classes
#define MM   (BB*TT)      // 131072 rows for input GEMM

#define SA 260            // sAs row stride (floats)

// ---------------- scratch (device globals; no allocs allowed) ----------------
__device__ float g_GX[(size_t)MM * GG];      // 512 MB layer-0 pregates [b][t][gate]
__device__ float g_H0b[2][BB * HH];          // layer-0 h double buffer
__device__ float g_H1b[2][BB * HH];          // layer-1 h double buffer
__device__ unsigned int g_bars[8 * 32];      // per-row-group barrier counters

// ---------------- packed f32x2 helpers (Blackwell FFMA2 path) ----------------
__device__ __forceinline__ ull pack2(float x, float y) {
    ull r;
    asm("mov.b64 %0, {%1, %2};" : "=l"(r) : "f"(x), "f"(y));
    return r;
}
__device__ __forceinline__ float2 unpack2(ull v) {
    float2 r;
    asm("mov.b64 {%0, %1}, %2;" : "=f"(r.x), "=f"(r.y) : "l"(v));
    return r;
}
__device__ __forceinline__ ull ffma2x(ull a, ull b, ull c) {
    ull d;
    asm("fma.rn.f32x2 %0, %1, %2, %3;" : "=l"(d) : "l"(a), "l"(b), "l"(c));
    return d;
}

// fast activations (error ~1e-6, well inside 1e-3 budget)
__device__ __forceinline__ float fsigm(float x) {
    float e = __expf(-x);
    return __fdividef(1.0f, 1.0f + e);
}
__device__ __forceinline__ float ftanh(float x) {
    float e = __expf(2.0f * x);           // overflow -> inf -> result 1 (correct)
    return 1.0f - __fdividef(2.0f, e + 1.0f);
}

__device__ __forceinline__ unsigned int ld_acquire_u(const unsigned int* p) {
    unsigned int v;
    asm volatile("ld.global.acquire.gpu.u32 %0, [%1];" : "=r"(v) : "l"(p) : "memory");
    return v;
}

// ---------------- big GEMM (layer-0 pregates only) ----------------------------
// g_GX[m,n] = sum_k x[m,k]*W[n,k] + b1[n] + b2[n].  EXACT R10/R13 structure
// (measured best 1.45ms, fma 59%), plus folded reset of the barrier flags.
__global__ void __launch_bounds__(256) gemm_gx(const float* __restrict__ A,
                                               const float* __restrict__ W,
                                               const float* __restrict__ b1,
                                               const float* __restrict__ b2) {
    __shared__ __align__(16) float As[2][16][128];
    __shared__ __align__(16) float Bs[2][16][64];

    const int tid = threadIdx.x;

    if (blockIdx.x == 0 && blockIdx.y == 0 && tid < 8 * 32)
        g_bars[tid] = 0u;

    float* __restrict__ Cout = g_GX;

    const int ty = tid >> 4;          // 0..15  (m group of 8)
    const int tx = tid & 15;          // 0..15  (n group of 4)
    const int bm0 = blockIdx.y * 128;
    const int bn0 = blockIdx.x * 64;

    const int a_row0 = tid >> 2;              // 0..63
    const int a_kg   = (tid & 3) * 4;
    const int b_row  = tid >> 2;
    const int b_kg   = (tid & 3) * 4;

    ull acc[4][4];
    #pragma unroll
    for (int i = 0; i < 4; i++)
        #pragma unroll
        for (int j = 0; j < 4; j++) acc[i][j] = 0ull;

    {
        #pragma unroll
        for (int i = 0; i < 2; i++) {
            int row = a_row0 + i * 64;
            float4 v = *(const float4*)&A[(size_t)(bm0 + row) * 256 + a_kg];
            As[0][a_kg + 0][row] = v.x; As[0][a_kg + 1][row] = v.y;
            As[0][a_kg + 2][row] = v.z; As[0][a_kg + 3][row] = v.w;
        }
        float4 v = *(const float4*)&W[(size_t)(bn0 + b_row) * 256 + b_kg];
        Bs[0][b_kg + 0][b_row] = v.x; Bs[0][b_kg + 1][b_row] = v.y;
        Bs[0][b_kg + 2][b_row] = v.z; Bs[0][b_kg + 3][b_row] = v.w;
    }
    __syncthreads();

    int buf = 0;
    for (int k0 = 0; k0 < 256; k0 += 16) {
        float4 pa0, pa1, pb;
        const bool more = (k0 + 16) < 256;
        if (more) {
            pa0 = *(const float4*)&A[(size_t)(bm0 + a_row0) * 256 + k0 + 16 + a_kg];
            pa1 = *(const float4*)&A[(size_t)(bm0 + a_row0 + 64) * 256 + k0 + 16 + a_kg];
            pb  = *(const float4*)&W[(size_t)(bn0 + b_row) * 256 + k0 + 16 + b_kg];
        }

        #pragma unroll
        for (int k = 0; k < 16; k++) {
            const ull* ap = (const ull*)&As[buf][k][ty * 8];
            ull a0 = ap[0], a1 = ap[1], a2 = ap[2], a3 = ap[3];
            float4 bv = *(const float4*)&Bs[buf][k][tx * 4];
            ull bb0 = pack2(bv.x, bv.x);
            ull bb1 = pack2(bv.y, bv.y);
            ull bb2 = pack2(bv.z, bv.z);
            ull bb3 = pack2(bv.w, bv.w);
            acc[0][0] = ffma2x(a0, bb0, acc[0][0]);
            acc[1][0] = ffma2x(a1, bb0, acc[1][0]);
            acc[2][0] = ffma2x(a2, bb0, acc[2][0]);
            acc[3][0] = ffma2x(a3, bb0, acc[3][0]);
            acc[0][1] = ffma2x(a0, bb1, acc[0][1]);
            acc[1][1] = ffma2x(a1, bb1, acc[1][1]);
            acc[2][1] = ffma2x(a2, bb1, acc[2][1]);
            acc[3][1] = ffma2x(a3, bb1, acc[3][1]);
            acc[0][2] = ffma2x(a0, bb2, acc[0][2]);
            acc[1][2] = ffma2x(a1, bb2, acc[1][2]);
            acc[2][2] = ffma2x(a2, bb2, acc[2][2]);
            acc[3][2] = ffma2x(a3, bb2, acc[3][2]);
            acc[0][3] = ffma2x(a0, bb3, acc[0][3]);
            acc[1][3] = ffma2x(a1, bb3, acc[1][3]);
            acc[2][3] = ffma2x(a2, bb3, acc[2][3]);
            acc[3][3] = ffma2x(a3, bb3, acc[3][3]);
        }

        if (more) {
            int nb = buf ^ 1;
            As[nb][a_kg + 0][a_row0] = pa0.x; As[nb][a_kg + 1][a_row0] = pa0.y;
            As[nb][a_kg + 2][a_row0] = pa0.z; As[nb][a_kg + 3][a_row0] = pa0.w;
            As[nb][a_kg + 0][a_row0 + 64] = pa1.x; As[nb][a_kg + 1][a_row0 + 64] = pa1.y;
            As[nb][a_kg + 2][a_row0 + 64] = pa1.z; As[nb][a_kg + 3][a_row0 + 64] = pa1.w;
            Bs[nb][b_kg + 0][b_row] = pb.x; Bs[nb][b_kg + 1][b_row] = pb.y;
            Bs[nb][b_kg + 2][b_row] = pb.z; Bs[nb][b_kg + 3][b_row] = pb.w;
            __syncthreads();
            buf = nb;
        }
    }

    float4 b1v = *(const float4*)&b1[bn0 + tx * 4];
    float4 b2v = *(const float4*)&b2[bn0 + tx * 4];
    float4 bias = make_float4(b1v.x + b2v.x, b1v.y + b2v.y,
                              b1v.z + b2v.z, b1v.w + b2v.w);
    #pragma unroll
    for (int i = 0; i < 4; i++) {
        float2 q0 = unpack2(acc[i][0]);
        float2 q1 = unpack2(acc[i][1]);
        float2 q2 = unpack2(acc[i][2]);
        float2 q3 = unpack2(acc[i][3]);
        size_t r0 = (size_t)(bm0 + ty * 8 + 2 * i);
        float4 v0 = make_float4(q0.x + bias.x, q1.x + bias.y, q2.x + bias.z, q3.x + bias.w);
        float4 v1 = make_float4(q0.y + bias.x, q1.y + bias.y, q2.y + bias.z, q3.y + bias.w);
        *(float4*)&Cout[r0 * GG + bn0 + tx * 4] = v0;
        *(float4*)&Cout[(r0 + 1) * GG + bn0 + tx * 4] = v1;
    }
}

// ---------------- dual-layer pipelined persistent recurrence ------------------
// ONE kernel runs BOTH LSTM layers, layer 1 trailing layer 0 by one step:
// interval tau: h0[tau] (layer-0 cell) ; gx1[tau-1] = h0[tau-1]@Wih1^T (fused
// input GEMM, registers only) ; h1[tau-1] (layer-1 cell, consumes gx1 regs).
// 513 intervals instead of 1024 serialized steps -> per-step chain overhead
// paid once per pair. 128 CTAs x 128 threads (R13 measured-best mapping):
// CTA = 32 rows x 16 cols, thread = 4 rows x 1 col, gate-pairs as f32x2.
// smem: Whh0+Wih1+Whh1 (192KB) + one reused h tile (33KB) = 229888 B.
__global__ void __launch_bounds__(128, 1) lstm_dual(const float* __restrict__ whh0,
                                                    const float* __restrict__ wih1,
                                                    const float* __restrict__ whh1,
                                                    const float* __restrict__ bi1,
                                                    const float* __restrict__ bh1) {
    extern __shared__ float sm[];
    float* sW0 = sm;                  // [256][64]  Whh0 [k][cl*4+g]
    float* sWi = sm + 256 * 64;       // [256][64]  Wih1
    float* sW1 = sm + 2 * 256 * 64;   // [256][64]  Whh1
    float* sAs = sm + 3 * 256 * 64;   // [32][SA]   h tile (reused both layers)

    const int tid  = threadIdx.x;
    const int bid  = blockIdx.x;
    const int hcol = tid & 15;
    const int rq   = tid >> 4;               // 0..7
    const int c0   = (bid & 15) * 16;        // h-col group
    const int grp  = bid >> 4;               // row group 0..7
    const int bm   = grp * 32;               // batch rows
    const int col  = c0 + hcol;

    // one-time weight stage: 64 gate-rows (cl*4+g) x 256 k, all three matrices
    for (int i = tid; i < 64 * 64; i += 128) {
        int lr = i >> 6;              // 0..63 local row (cl*4+g)
        int kk = (i & 63) * 4;        // k0
        int bh = lr >> 2, g = lr & 3;
        size_t off = (size_t)(g * HH + c0 + bh) * HH + kk;
        float4 v0 = *(const float4*)&whh0[off];
        sW0[(kk + 0) * 64 + lr] = v0.x;
        sW0[(kk + 1) * 64 + lr] = v0.y;
        sW0[(kk + 2) * 64 + lr] = v0.z;
        sW0[(kk + 3) * 64 + lr] = v0.w;
        float4 vi = *(const float4*)&wih1[off];
        sWi[(kk + 0) * 64 + lr] = vi.x;
        sWi[(kk + 1) * 64 + lr] = vi.y;
        sWi[(kk + 2) * 64 + lr] = vi.z;
        sWi[(kk + 3) * 64 + lr] = vi.w;
        float4 v1 = *(const float4*)&whh1[off];
        sW1[(kk + 0) * 64 + lr] = v1.x;
        sW1[(kk + 1) * 64 + lr] = v1.y;
        sW1[(kk + 2) * 64 + lr] = v1.z;
        sW1[(kk + 3) * 64 + lr] = v1.w;
    }
    __syncthreads();

    // layer-1 biases for this thread's column
    const float nb_i = bi1[col]       + bh1[col];
    const float nb_f = bi1[256 + col] + bh1[256 + col];
    const float nb_g = bi1[512 + col] + bh1[512 + col];
    const float nb_o = bi1[768 + col] + bh1[768 + col];

    float creg0[4] = {0.f, 0.f, 0.f, 0.f};
    float creg1[4] = {0.f, 0.f, 0.f, 0.f};
    int rows[4];
    #pragma unroll
    for (int r = 0; r < 4; r++) rows[r] = bm + rq * 4 + r;

    // t=0 layer-0 pregate prefetch (GX layout [b][t][gate])
    float pg_i[4], pg_f[4], pg_g[4], pg_o[4];
    #pragma unroll
    for (int r = 0; r < 4; r++) {
        size_t base = (size_t)rows[r] * TT * GG + col;   // t=0
        pg_i[r] = g_GX[base];
        pg_f[r] = g_GX[base + 256];
        pg_g[r] = g_GX[base + 512];
        pg_o[r] = g_GX[base + 768];
    }

    const int sr  = tid & 31;          // staging row 0..31
    const int skc = tid >> 5;          // staging k-chunk 0..3 (64 floats each)

    unsigned int* barp = &g_bars[grp * 32];

    for (int tau = 0; tau <= TT; tau++) {
        ull aif[4] = {0, 0, 0, 0};     // L0 recurrent (i,f),(g,o)
        ull ago[4] = {0, 0, 0, 0};
        ull bif[4] = {0, 0, 0, 0};     // gx1 (i,f),(g,o)
        ull bgo[4] = {0, 0, 0, 0};
        ull cif[4] = {0, 0, 0, 0};     // L1 recurrent (i,f),(g,o)
        ull cgo[4] = {0, 0, 0, 0};

        // ---- phase A: stage h0[tau-1]; L0 recurrent + gx1 ----
        if (tau >= 1) {
            {
                const float* hsrc = g_H0b[(tau - 1) & 1];
                const float* hrow = &hsrc[(bm + sr) * HH + skc * 64];
                float* dst = &sAs[sr * SA + skc * 64];
                #pragma unroll
                for (int j = 0; j < 16; j++)
                    *(float4*)&dst[j * 4] = *(const float4*)&hrow[j * 4];
            }
            __syncthreads();

            const float* hr0 = &sAs[(rq * 4 + 0) * SA];
            const float* hr1 = &sAs[(rq * 4 + 1) * SA];
            const float* hr2 = &sAs[(rq * 4 + 2) * SA];
            const float* hr3 = &sAs[(rq * 4 + 3) * SA];
            const float* bpW = &sW0[hcol * 4];
            const float* bpI = &sWi[hcol * 4];

            if (tau < TT) {
                #pragma unroll 2
                for (int k4 = 0; k4 < 256; k4 += 4) {
                    float hv0[4], hv1[4], hv2[4], hv3[4];
                    *(float4*)hv0 = *(const float4*)&hr0[k4];
                    *(float4*)hv1 = *(const float4*)&hr1[k4];
                    *(float4*)hv2 = *(const float4*)&hr2[k4];
                    *(float4*)hv3 = *(const float4*)&hr3[k4];
                    #pragma unroll
                    for (int j = 0; j < 4; j++) {
                        ulonglong2 wv = *(const ulonglong2*)(bpW + (k4 + j) * 64);
                        ulonglong2 wi = *(const ulonglong2*)(bpI + (k4 + j) * 64);
                        ull a0 = pack2(hv0[j], hv0[j]);
                        ull a1 = pack2(hv1[j], hv1[j]);
                        ull a2 = pack2(hv2[j], hv2[j]);
                        ull a3 = pack2(hv3[j], hv3[j]);
                        aif[0] = ffma2x(a0, wv.x, aif[0]);
                        ago[0] = ffma2x(a0, wv.y, ago[0]);
                        bif[0] = ffma2x(a0, wi.x, bif[0]);
                        bgo[0] = ffma2x(a0, wi.y, bgo[0]);
                        aif[1] = ffma2x(a1, wv.x, aif[1]);
                        ago[1] = ffma2x(a1, wv.y, ago[1]);
                        bif[1] = ffma2x(a1, wi.x, bif[1]);
                        bgo[1] = ffma2x(a1, wi.y, bgo[1]);
                        aif[2] = ffma2x(a2, wv.x, aif[2]);
                        ago[2] = ffma2x(a2, wv.y, ago[2]);
                        bif[2] = ffma2x(a2, wi.x, bif[2]);
                        bgo[2] = ffma2x(a2, wi.y, bgo[2]);
                        aif[3] = ffma2x(a3, wv.x, aif[3]);
                        ago[3] = ffma2x(a3, wv.y, ago[3]);
                        bif[3] = ffma2x(a3, wi.x, bif[3]);
                        bgo[3] = ffma2x(a3, wi.y, bgo[3]);
                    }
                }
            } else {
                // tail: gx1[511] only
                #pragma unroll 4
                for (int k4 = 0; k4 < 256; k4 += 4) {
                    float hv0[4], hv1[4], hv2[4], hv3[4];
                    *(float4*)hv0 = *(const float4*)&hr0[k4];
                    *(float4*)hv1 = *(const float4*)&hr1[k4];
                    *(float4*)hv2 = *(const float4*)&hr2[k4];
                    *(float4*)hv3 = *(const float4*)&hr3[k4];
                    #pragma unroll
                    for (int j = 0; j < 4; j++) {
                        ulonglong2 wi = *(const ulonglong2*)(bpI + (k4 + j) * 64);
                        ull a0 = pack2(hv0[j], hv0[j]);
                        ull a1 = pack2(hv1[j], hv1[j]);
                        ull a2 = pack2(hv2[j], hv2[j]);
                        ull a3 = pack2(hv3[j], hv3[j]);
                        bif[0] = ffma2x(a0, wi.x, bif[0]);
                        bgo[0] = ffma2x(a0, wi.y, bgo[0]);
                        bif[1] = ffma2x(a1, wi.x, bif[1]);
                        bgo[1] = ffma2x(a1, wi.y, bgo[1]);
                        bif[2] = ffma2x(a2, wi.x, bif[2]);
                        bgo[2] = ffma2x(a2, wi.y, bgo[2]);
                        bif[3] = ffma2x(a3, wi.x, bif[3]);
                        bgo[3] = ffma2x(a3, wi.y, bgo[3]);
                    }
                }
            }
            __syncthreads();   // sAs reused by phase B
        }

        // ---- layer-0 epilogue: h0[tau] ----
        if (tau < TT) {
            float* hout0 = g_H0b[tau & 1];
            #pragma unroll
            for (int r = 0; r < 4; r++) {
                float2 fif = unpack2(aif[r]);
                float2 fgo = unpack2(ago[r]);
                float si = fsigm(fif.x + pg_i[r]);
                float sf = fsigm(fif.y + pg_f[r]);
                float tg = ftanh(fgo.x + pg_g[r]);
                float so = fsigm(fgo.y + pg_o[r]);
                float c  = sf * creg0[r] + si * tg;
                creg0[r] = c;
                hout0[rows[r] * HH + col] = so * ftanh(c);
            }
        }

        // ---- phase B: stage h1[tau-2]; L1 recurrent ----
        if (tau >= 2) {
            {
                const float* hsrc = g_H1b[tau & 1];   // (tau-2)&1 == tau&1
                const float* hrow = &hsrc[(bm + sr) * HH + skc * 64];
                float* dst = &sAs[sr * SA + skc * 64];
                #pragma unroll
                for (int j = 0; j < 16; j++)
                    *(float4*)&dst[j * 4] = *(const float4*)&hrow[j * 4];
            }
            __syncthreads();

            const float* hr0 = &sAs[(rq * 4 + 0) * SA];
            const float* hr1 = &sAs[(rq * 4 + 1) * SA];
            const float* hr2 = &sAs[(rq * 4 + 2) * SA];
            const float* hr3 = &sAs[(rq * 4 + 3) * SA];
            const float* bpW = &sW1[hcol * 4];

            #pragma unroll 4
            for (int k4 = 0; k4 < 256; k4 += 4) {
                float hv0[4], hv1[4], hv2[4], hv3[4];
                *(float4*)hv0 = *(const float4*)&hr0[k4];
                *(float4*)hv1 = *(const float4*)&hr1[k4];
                *(float4*)hv2 = *(const float4*)&hr2[k4];
                *(float4*)hv3 = *(const float4*)&hr3[k4];
                #pragma unroll
                for (int j = 0; j < 4; j++) {
                    ulonglong2 wv = *(const ulonglong2*)(bpW + (k4 + j) * 64);
                    ull a0 = pack2(hv0[j], hv0[j]);
                    ull a1 = pack2(hv1[j], hv1[j]);
                    ull a2 = pack2(hv2[j], hv2[j]);
                    ull a3 = pack2(hv3[j], hv3[j]);
                    cif[0] = ffma2x(a0, wv.x, cif[0]);
                    cgo[0] = ffma2x(a0, wv.y, cgo[0]);
                    cif[1] = ffma2x(a1, wv.x, cif[1]);
                    cgo[1] = ffma2x(a1, wv.y, cgo[1]);
                    cif[2] = ffma2x(a2, wv.x, cif[2]);
                    cgo[2] = ffma2x(a2, wv.y, cgo[2]);
                    cif[3] = ffma2x(a3, wv.x, cif[3]);
                    cgo[3] = ffma2x(a3, wv.y, cgo[3]);
                }
            }
        }

        // ---- layer-1 epilogue: h1[tau-1], pregates from registers ----
        if (tau >= 1) {
            float* hout1 = g_H1b[(tau - 1) & 1];
            #pragma unroll
            for (int r = 0; r < 4; r++) {
                float2 rif = unpack2(cif[r]);
                float2 rgo = unpack2(cgo[r]);
                float2 xif = unpack2(bif[r]);
                float2 xgo = unpack2(bgo[r]);
                float si = fsigm(rif.x + xif.x + nb_i);
                float sf = fsigm(rif.y + xif.y + nb_f);
                float tg = ftanh(rgo.x + xgo.x + nb_g);
                float so = fsigm(rgo.y + xgo.y + nb_o);
                float c  = sf * creg1[r] + si * tg;
                creg1[r] = c;
                hout1[rows[r] * HH + col] = so * ftanh(c);
            }
        }

        // ---- per-row-group barrier (16 CTAs per counter) ----
        if (tau < TT) {
            __syncthreads();                       // all reads + h stores done
            if (tid == 0) {
                __threadfence();                   // release h to GPU scope
                atomicAdd(barp, 1u);
            }
            // prefetch next interval's layer-0 pregates while peers arrive
            if (tau + 1 < TT) {
                #pragma unroll
                for (int r = 0; r < 4; r++) {
                    size_t base = ((size_t)rows[r] * TT + (tau + 1)) * GG + col;
                    pg_i[r] = g_GX[base];
                    pg_f[r] = g_GX[base + 256];
                    pg_g[r] = g_GX[base + 512];
                    pg_o[r] = g_GX[base + 768];
                }
            }
            if (tid == 0) {
                unsigned target = (unsigned)(tau + 1) * 16u;
                while (ld_acquire_u(barp) < target) { }
            }
            __syncthreads();
        }
    }
}

// ---------------- FC + log_softmax ------------------------------------------
__global__ void __launch_bounds__(128) fc_kernel(const float* __restrict__ wfc,
                                                 const float* __restrict__ bfc,
                                                 float* __restrict__ out) {
    const int b = blockIdx.x;
    const int tid = threadIdx.x;  // 128 = one class per thread
    __shared__ float h[256];
    // h1[511] written at tau=512 with parity (512-1)&1 = 1
    h[tid] = g_H1b[1][b * HH + tid];
    h[tid + 128] = g_H1b[1][b * HH + tid + 128];
    __syncthreads();

    float acc = bfc[tid];
    const float* wp = wfc + (size_t)tid * HH;
    #pragma unroll 8
    for (int k = 0; k < 256; k++) acc += h[k] * wp[k];

    float m = acc;
    #pragma unroll
    for (int o = 16; o > 0; o >>= 1)
        m = fmaxf(m, __shfl_xor_sync(0xffffffffu, m, o));
    __shared__ float smax[4], ssum[4];
    int wid = tid >> 5, lane = tid & 31;
    if (lane == 0) smax[wid] = m;
    __syncthreads();
    m = fmaxf(fmaxf(smax[0], smax[1]), fmaxf(smax[2], smax[3]));

    float e = expf(acc - m);
    float s = e;
    #pragma unroll
    for (int o = 16; o > 0; o >>= 1)
        s += __shfl_xor_sync(0xffffffffu, s, o);
    if (lane == 0) ssum[wid] = s;
    __syncthreads();
    s = ssum[0] + ssum[1] + ssum[2] + ssum[3];

    out[b * CC + tid] = acc - m - logf(s);
}

// ---------------- launch ------------------------------------------------------
extern "C" void kernel_launch(void* const* d_in, const int* in_sizes, int n_in,
                              void* d_out, int out_size) {
    const float* x    = (const float*)d_in[0];
    const float* wih0 = (const float*)d_in[1];
    const float* whh0 = (const float*)d_in[2];
    const float* bih0 = (const float*)d_in[3];
    const float* bhh0 = (const float*)d_in[4];
    const float* wih1 = (const float*)d_in[5];
    const float* whh1 = (const float*)d_in[6];
    const float* bih1 = (const float*)d_in[7];
    const float* bhh1 = (const float*)d_in[8];
    const float* wfc  = (const float*)d_in[9];
    const float* bfc  = (const float*)d_in[10];
    float* out = (float*)d_out;

    const int dual_smem = (3 * 256 * 64 + 32 * SA) * (int)sizeof(float); // 229888 B
    cudaFuncSetAttribute(lstm_dual,
                         cudaFuncAttributeMaxDynamicSharedMemorySize,
                         dual_smem);

    dim3 gemm_grid(16, 1024);   // N/64, M/128

    // 3 launches total: gemm0 -> lstm_dual (both layers pipelined) -> fc
    gemm_gx<<<gemm_grid, 256>>>(x, wih0, bih0, bhh0);
    lstm_dual<<<128, 128, dual_smem>>>(whh0, wih1, whh1, bih1, bhh1);
    fc_kernel<<<256, 128>>>(wfc, bfc, out);
}

// round 16
// speedup vs baseline: 1.1813x; 1.0189x over previous
#include <cuda_runtime.h>
#include <cuda_bf16.h>
#include <math.h>

typedef unsigned long long ull;

// Problem constants
#define BB   256          // batch
#define TT   512          // seq len
#define HH   256          // hidden
#define GG   1024         // 4*H gates
#define CC   128          // classes
#define MM   (BB*TT)      // 131072 rows for input GEMM

#define SA 260            // sAs row stride (floats)

// ---------------- scratch (device globals; no allocs allowed) ----------------
__device__ float g_GX[(size_t)MM * GG];      // 512 MB layer-0 pregates [b][t][gate]
__device__ float g_H0b[2][BB * HH];          // layer-0 h double buffer
__device__ float g_H1b[2][BB * HH];          // layer-1 h double buffer
__device__ unsigned int g_bars[8 * 32];      // per-row-group barrier counters

// ---------------- packed f32x2 helpers (Blackwell FFMA2 path) ----------------
__device__ __forceinline__ ull pack2(float x, float y) {
    ull r;
    asm("mov.b64 %0, {%1, %2};" : "=l"(r) : "f"(x), "f"(y));
    return r;
}
__device__ __forceinline__ float2 unpack2(ull v) {
    float2 r;
    asm("mov.b64 {%0, %1}, %2;" : "=f"(r.x), "=f"(r.y) : "l"(v));
    return r;
}
__device__ __forceinline__ ull ffma2x(ull a, ull b, ull c) {
    ull d;
    asm("fma.rn.f32x2 %0, %1, %2, %3;" : "=l"(d) : "l"(a), "l"(b), "l"(c));
    return d;
}

// fast activations (error ~1e-6, well inside 1e-3 budget)
__device__ __forceinline__ float fsigm(float x) {
    float e = __expf(-x);
    return __fdividef(1.0f, 1.0f + e);
}
__device__ __forceinline__ float ftanh(float x) {
    float e = __expf(2.0f * x);           // overflow -> inf -> result 1 (correct)
    return 1.0f - __fdividef(2.0f, e + 1.0f);
}

__device__ __forceinline__ unsigned int ld_acquire_u(const unsigned int* p) {
    unsigned int v;
    asm volatile("ld.global.acquire.gpu.u32 %0, [%1];" : "=r"(v) : "l"(p) : "memory");
    return v;
}

// ---------------- big GEMM (layer-0 pregates only) ----------------------------
// g_GX[m,n] = sum_k x[m,k]*W[n,k] + b1[n] + b2[n].  EXACT R10/R15 structure
// (measured best 1.45ms, fma 59%), plus folded reset of the barrier flags.
__global__ void __launch_bounds__(256) gemm_gx(const float* __restrict__ A,
                                               const float* __restrict__ W,
                                               const float* __restrict__ b1,
                                               const float* __restrict__ b2) {
    __shared__ __align__(16) float As[2][16][128];
    __shared__ __align__(16) float Bs[2][16][64];

    const int tid = threadIdx.x;

    if (blockIdx.x == 0 && blockIdx.y == 0 && tid < 8 * 32)
        g_bars[tid] = 0u;

    float* __restrict__ Cout = g_GX;

    const int ty = tid >> 4;          // 0..15  (m group of 8)
    const int tx = tid & 15;          // 0..15  (n group of 4)
    const int bm0 = blockIdx.y * 128;
    const int bn0 = blockIdx.x * 64;

    const int a_row0 = tid >> 2;              // 0..63
    const int a_kg   = (tid & 3) * 4;
    const int b_row  = tid >> 2;
    const int b_kg   = (tid & 3) * 4;

    ull acc[4][4];
    #pragma unroll
    for (int i = 0; i < 4; i++)
        #pragma unroll
        for (int j = 0; j < 4; j++) acc[i][j] = 0ull;

    {
        #pragma unroll
        for (int i = 0; i < 2; i++) {
            int row = a_row0 + i * 64;
            float4 v = *(const float4*)&A[(size_t)(bm0 + row) * 256 + a_kg];
            As[0][a_kg + 0][row] = v.x; As[0][a_kg + 1][row] = v.y;
            As[0][a_kg + 2][row] = v.z; As[0][a_kg + 3][row] = v.w;
        }
        float4 v = *(const float4*)&W[(size_t)(bn0 + b_row) * 256 + b_kg];
        Bs[0][b_kg + 0][b_row] = v.x; Bs[0][b_kg + 1][b_row] = v.y;
        Bs[0][b_kg + 2][b_row] = v.z; Bs[0][b_kg + 3][b_row] = v.w;
    }
    __syncthreads();

    int buf = 0;
    for (int k0 = 0; k0 < 256; k0 += 16) {
        float4 pa0, pa1, pb;
        const bool more = (k0 + 16) < 256;
        if (more) {
            pa0 = *(const float4*)&A[(size_t)(bm0 + a_row0) * 256 + k0 + 16 + a_kg];
            pa1 = *(const float4*)&A[(size_t)(bm0 + a_row0 + 64) * 256 + k0 + 16 + a_kg];
            pb  = *(const float4*)&W[(size_t)(bn0 + b_row) * 256 + k0 + 16 + b_kg];
        }

        #pragma unroll
        for (int k = 0; k < 16; k++) {
            const ull* ap = (const ull*)&As[buf][k][ty * 8];
            ull a0 = ap[0], a1 = ap[1], a2 = ap[2], a3 = ap[3];
            float4 bv = *(const float4*)&Bs[buf][k][tx * 4];
            ull bb0 = pack2(bv.x, bv.x);
            ull bb1 = pack2(bv.y, bv.y);
            ull bb2 = pack2(bv.z, bv.z);
            ull bb3 = pack2(bv.w, bv.w);
            acc[0][0] = ffma2x(a0, bb0, acc[0][0]);
            acc[1][0] = ffma2x(a1, bb0, acc[1][0]);
            acc[2][0] = ffma2x(a2, bb0, acc[2][0]);
            acc[3][0] = ffma2x(a3, bb0, acc[3][0]);
            acc[0][1] = ffma2x(a0, bb1, acc[0][1]);
            acc[1][1] = ffma2x(a1, bb1, acc[1][1]);
            acc[2][1] = ffma2x(a2, bb1, acc[2][1]);
            acc[3][1] = ffma2x(a3, bb1, acc[3][1]);
            acc[0][2] = ffma2x(a0, bb2, acc[0][2]);
            acc[1][2] = ffma2x(a1, bb2, acc[1][2]);
            acc[2][2] = ffma2x(a2, bb2, acc[2][2]);
            acc[3][2] = ffma2x(a3, bb2, acc[3][2]);
            acc[0][3] = ffma2x(a0, bb3, acc[0][3]);
            acc[1][3] = ffma2x(a1, bb3, acc[1][3]);
            acc[2][3] = ffma2x(a2, bb3, acc[2][3]);
            acc[3][3] = ffma2x(a3, bb3, acc[3][3]);
        }

        if (more) {
            int nb = buf ^ 1;
            As[nb][a_kg + 0][a_row0] = pa0.x; As[nb][a_kg + 1][a_row0] = pa0.y;
            As[nb][a_kg + 2][a_row0] = pa0.z; As[nb][a_kg + 3][a_row0] = pa0.w;
            As[nb][a_kg + 0][a_row0 + 64] = pa1.x; As[nb][a_kg + 1][a_row0 + 64] = pa1.y;
            As[nb][a_kg + 2][a_row0 + 64] = pa1.z; As[nb][a_kg + 3][a_row0 + 64] = pa1.w;
            Bs[nb][b_kg + 0][b_row] = pb.x; Bs[nb][b_kg + 1][b_row] = pb.y;
            Bs[nb][b_kg + 2][b_row] = pb.z; Bs[nb][b_kg + 3][b_row] = pb.w;
            __syncthreads();
            buf = nb;
        }
    }

    float4 b1v = *(const float4*)&b1[bn0 + tx * 4];
    float4 b2v = *(const float4*)&b2[bn0 + tx * 4];
    float4 bias = make_float4(b1v.x + b2v.x, b1v.y + b2v.y,
                              b1v.z + b2v.z, b1v.w + b2v.w);
    #pragma unroll
    for (int i = 0; i < 4; i++) {
        float2 q0 = unpack2(acc[i][0]);
        float2 q1 = unpack2(acc[i][1]);
        float2 q2 = unpack2(acc[i][2]);
        float2 q3 = unpack2(acc[i][3]);
        size_t r0 = (size_t)(bm0 + ty * 8 + 2 * i);
        float4 v0 = make_float4(q0.x + bias.x, q1.x + bias.y, q2.x + bias.z, q3.x + bias.w);
        float4 v1 = make_float4(q0.y + bias.x, q1.y + bias.y, q2.y + bias.z, q3.y + bias.w);
        *(float4*)&Cout[r0 * GG + bn0 + tx * 4] = v0;
        *(float4*)&Cout[(r0 + 1) * GG + bn0 + tx * 4] = v1;
    }
}

// ---------------- dual-layer pipelined persistent recurrence ------------------
// ONE kernel runs BOTH LSTM layers, layer 1 trailing layer 0 by one step
// (R15 structure, measured best). NEW in R16: warp-disjoint weight columns —
// warp w owns cols {4w..4w+3}; lane = (c = lane>>3, rq = lane&7); thread =
// 1 col x 4 rows (rows rq+8i). Weight LDS per warp per k = 64B contiguous =
// 1 wavefront (was 2, all warps reading all 16 cols): weight crossbar halves
// (6144 -> 3072 cyc/interval). Rows at rq+8i keep h-LDS.128 conflict-free
// with SA=260 (bank = (rq*4+c) mod 32 spans all eight 4-bank groups).
__global__ void __launch_bounds__(128, 1) lstm_dual(const float* __restrict__ whh0,
                                                    const float* __restrict__ wih1,
                                                    const float* __restrict__ whh1,
                                                    const float* __restrict__ bi1,
                                                    const float* __restrict__ bh1) {
    extern __shared__ float sm[];
    float* sW0 = sm;                  // [256][64]  Whh0 [k][cl*4+g]
    float* sWi = sm + 256 * 64;       // [256][64]  Wih1
    float* sW1 = sm + 2 * 256 * 64;   // [256][64]  Whh1
    float* sAs = sm + 3 * 256 * 64;   // [32][SA]   h tile (reused both layers)

    const int tid  = threadIdx.x;
    const int bid  = blockIdx.x;
    const int w    = tid >> 5;                     // warp 0..3
    const int lane = tid & 31;
    const int hcol = (w << 2) | (lane >> 3);       // warp-disjoint col 0..15
    const int rq   = lane & 7;                     // row base 0..7
    const int c0   = (bid & 15) * 16;              // h-col group
    const int grp  = bid >> 4;                     // row group 0..7
    const int bm   = grp * 32;                     // batch rows
    const int col  = c0 + hcol;

    // one-time weight stage: 64 gate-rows (cl*4+g) x 256 k, all three matrices
    for (int i = tid; i < 64 * 64; i += 128) {
        int lr = i >> 6;              // 0..63 local row (cl*4+g)
        int kk = (i & 63) * 4;        // k0
        int bh = lr >> 2, g = lr & 3;
        size_t off = (size_t)(g * HH + c0 + bh) * HH + kk;
        float4 v0 = *(const float4*)&whh0[off];
        sW0[(kk + 0) * 64 + lr] = v0.x;
        sW0[(kk + 1) * 64 + lr] = v0.y;
        sW0[(kk + 2) * 64 + lr] = v0.z;
        sW0[(kk + 3) * 64 + lr] = v0.w;
        float4 vi = *(const float4*)&wih1[off];
        sWi[(kk + 0) * 64 + lr] = vi.x;
        sWi[(kk + 1) * 64 + lr] = vi.y;
        sWi[(kk + 2) * 64 + lr] = vi.z;
        sWi[(kk + 3) * 64 + lr] = vi.w;
        float4 v1 = *(const float4*)&whh1[off];
        sW1[(kk + 0) * 64 + lr] = v1.x;
        sW1[(kk + 1) * 64 + lr] = v1.y;
        sW1[(kk + 2) * 64 + lr] = v1.z;
        sW1[(kk + 3) * 64 + lr] = v1.w;
    }
    __syncthreads();

    // layer-1 biases for this thread's column
    const float nb_i = bi1[col]       + bh1[col];
    const float nb_f = bi1[256 + col] + bh1[256 + col];
    const float nb_g = bi1[512 + col] + bh1[512 + col];
    const float nb_o = bi1[768 + col] + bh1[768 + col];

    float creg0[4] = {0.f, 0.f, 0.f, 0.f};
    float creg1[4] = {0.f, 0.f, 0.f, 0.f};
    int rows[4];
    #pragma unroll
    for (int r = 0; r < 4; r++) rows[r] = bm + rq + 8 * r;

    // t=0 layer-0 pregate prefetch (GX layout [b][t][gate])
    float pg_i[4], pg_f[4], pg_g[4], pg_o[4];
    #pragma unroll
    for (int r = 0; r < 4; r++) {
        size_t base = (size_t)rows[r] * TT * GG + col;   // t=0
        pg_i[r] = g_GX[base];
        pg_f[r] = g_GX[base + 256];
        pg_g[r] = g_GX[base + 512];
        pg_o[r] = g_GX[base + 768];
    }

    const int sr  = tid & 31;          // staging row 0..31
    const int skc = tid >> 5;          // staging k-chunk 0..3 (64 floats each)

    unsigned int* barp = &g_bars[grp * 32];

    for (int tau = 0; tau <= TT; tau++) {
        ull aif[4] = {0, 0, 0, 0};     // L0 recurrent (i,f),(g,o)
        ull ago[4] = {0, 0, 0, 0};
        ull bif[4] = {0, 0, 0, 0};     // gx1 (i,f),(g,o)
        ull bgo[4] = {0, 0, 0, 0};
        ull cif[4] = {0, 0, 0, 0};     // L1 recurrent (i,f),(g,o)
        ull cgo[4] = {0, 0, 0, 0};

        // ---- phase A: stage h0[tau-1]; L0 recurrent + gx1 ----
        if (tau >= 1) {
            {
                const float* hsrc = g_H0b[(tau - 1) & 1];
                const float* hrow = &hsrc[(bm + sr) * HH + skc * 64];
                float* dst = &sAs[sr * SA + skc * 64];
                #pragma unroll
                for (int j = 0; j < 16; j++)
                    *(float4*)&dst[j * 4] = *(const float4*)&hrow[j * 4];
            }
            __syncthreads();

            const float* hr0 = &sAs[(rq + 0)  * SA];
            const float* hr1 = &sAs[(rq + 8)  * SA];
            const float* hr2 = &sAs[(rq + 16) * SA];
            const float* hr3 = &sAs[(rq + 24) * SA];
            const float* bpW = &sW0[hcol * 4];
            const float* bpI = &sWi[hcol * 4];

            if (tau < TT) {
                #pragma unroll 2
                for (int k4 = 0; k4 < 256; k4 += 4) {
                    float hv0[4], hv1[4], hv2[4], hv3[4];
                    *(float4*)hv0 = *(const float4*)&hr0[k4];
                    *(float4*)hv1 = *(const float4*)&hr1[k4];
                    *(float4*)hv2 = *(const float4*)&hr2[k4];
                    *(float4*)hv3 = *(const float4*)&hr3[k4];
                    #pragma unroll
                    for (int j = 0; j < 4; j++) {
                        ulonglong2 wv = *(const ulonglong2*)(bpW + (k4 + j) * 64);
                        ulonglong2 wi = *(const ulonglong2*)(bpI + (k4 + j) * 64);
                        ull a0 = pack2(hv0[j], hv0[j]);
                        ull a1 = pack2(hv1[j], hv1[j]);
                        ull a2 = pack2(hv2[j], hv2[j]);
                        ull a3 = pack2(hv3[j], hv3[j]);
                        aif[0] = ffma2x(a0, wv.x, aif[0]);
                        ago[0] = ffma2x(a0, wv.y, ago[0]);
                        bif[0] = ffma2x(a0, wi.x, bif[0]);
                        bgo[0] = ffma2x(a0, wi.y, bgo[0]);
                        aif[1] = ffma2x(a1, wv.x, aif[1]);
                        ago[1] = ffma2x(a1, wv.y, ago[1]);
                        bif[1] = ffma2x(a1, wi.x, bif[1]);
                        bgo[1] = ffma2x(a1, wi.y, bgo[1]);
                        aif[2] = ffma2x(a2, wv.x, aif[2]);
                        ago[2] = ffma2x(a2, wv.y, ago[2]);
                        bif[2] = ffma2x(a2, wi.x, bif[2]);
                        bgo[2] = ffma2x(a2, wi.y, bgo[2]);
                        aif[3] = ffma2x(a3, wv.x, aif[3]);
                        ago[3] = ffma2x(a3, wv.y, ago[3]);
                        bif[3] = ffma2x(a3, wi.x, bif[3]);
                        bgo[3] = ffma2x(a3, wi.y, bgo[3]);
                    }
                }
            } else {
                // tail: gx1[511] only
                #pragma unroll 4
                for (int k4 = 0; k4 < 256; k4 += 4) {
                    float hv0[4], hv1[4], hv2[4], hv3[4];
                    *(float4*)hv0 = *(const float4*)&hr0[k4];
                    *(float4*)hv1 = *(const float4*)&hr1[k4];
                    *(float4*)hv2 = *(const float4*)&hr2[k4];
                    *(float4*)hv3 = *(const float4*)&hr3[k4];
                    #pragma unroll
                    for (int j = 0; j < 4; j++) {
                        ulonglong2 wi = *(const ulonglong2*)(bpI + (k4 + j) * 64);
                        ull a0 = pack2(hv0[j], hv0[j]);
                        ull a1 = pack2(hv1[j], hv1[j]);
                        ull a2 = pack2(hv2[j], hv2[j]);
                        ull a3 = pack2(hv3[j], hv3[j]);
                        bif[0] = ffma2x(a0, wi.x, bif[0]);
                        bgo[0] = ffma2x(a0, wi.y, bgo[0]);
                        bif[1] = ffma2x(a1, wi.x, bif[1]);
                        bgo[1] = ffma2x(a1, wi.y, bgo[1]);
                        bif[2] = ffma2x(a2, wi.x, bif[2]);
                        bgo[2] = ffma2x(a2, wi.y, bgo[2]);
                        bif[3] = ffma2x(a3, wi.x, bif[3]);
                        bgo[3] = ffma2x(a3, wi.y, bgo[3]);
                    }
                }
            }
            __syncthreads();   // sAs reused by phase B
        }

        // ---- layer-0 epilogue: h0[tau] ----
        if (tau < TT) {
            float* hout0 = g_H0b[tau & 1];
            #pragma unroll
            for (int r = 0; r < 4; r++) {
                float2 fif = unpack2(aif[r]);
                float2 fgo = unpack2(ago[r]);
                float si = fsigm(fif.x + pg_i[r]);
                float sf = fsigm(fif.y + pg_f[r]);
                float tg = ftanh(fgo.x + pg_g[r]);
                float so = fsigm(fgo.y + pg_o[r]);
                float c  = sf * creg0[r] + si * tg;
                creg0[r] = c;
                hout0[rows[r] * HH + col] = so * ftanh(c);
            }
        }

        // ---- phase B: stage h1[tau-2]; L1 recurrent ----
        if (tau >= 2) {
            {
                const float* hsrc = g_H1b[tau & 1];   // (tau-2)&1 == tau&1
                const float* hrow = &hsrc[(bm + sr) * HH + skc * 64];
                float* dst = &sAs[sr * SA + skc * 64];
                #pragma unroll
                for (int j = 0; j < 16; j++)
                    *(float4*)&dst[j * 4] = *(const float4*)&hrow[j * 4];
            }
            __syncthreads();

            const float* hr0 = &sAs[(rq + 0)  * SA];
            const float* hr1 = &sAs[(rq + 8)  * SA];
            const float* hr2 = &sAs[(rq + 16) * SA];
            const float* hr3 = &sAs[(rq + 24) * SA];
            const float* bpW = &sW1[hcol * 4];

            #pragma unroll 4
            for (int k4 = 0; k4 < 256; k4 += 4) {
                float hv0[4], hv1[4], hv2[4], hv3[4];
                *(float4*)hv0 = *(const float4*)&hr0[k4];
                *(float4*)hv1 = *(const float4*)&hr1[k4];
                *(float4*)hv2 = *(const float4*)&hr2[k4];
                *(float4*)hv3 = *(const float4*)&hr3[k4];
                #pragma unroll
                for (int j = 0; j < 4; j++) {
                    ulonglong2 wv = *(const ulonglong2*)(bpW + (k4 + j) * 64);
                    ull a0 = pack2(hv0[j], hv0[j]);
                    ull a1 = pack2(hv1[j], hv1[j]);
                    ull a2 = pack2(hv2[j], hv2[j]);
                    ull a3 = pack2(hv3[j], hv3[j]);
                    cif[0] = ffma2x(a0, wv.x, cif[0]);
                    cgo[0] = ffma2x(a0, wv.y, cgo[0]);
                    cif[1] = ffma2x(a1, wv.x, cif[1]);
                    cgo[1] = ffma2x(a1, wv.y, cgo[1]);
                    cif[2] = ffma2x(a2, wv.x, cif[2]);
                    cgo[2] = ffma2x(a2, wv.y, cgo[2]);
                    cif[3] = ffma2x(a3, wv.x, cif[3]);
                    cgo[3] = ffma2x(a3, wv.y, cgo[3]);
                }
            }
        }

        // ---- layer-1 epilogue: h1[tau-1], pregates from registers ----
        if (tau >= 1) {
            float* hout1 = g_H1b[(tau - 1) & 1];
            #pragma unroll
            for (int r = 0; r < 4; r++) {
                float2 rif = unpack2(cif[r]);
                float2 rgo = unpack2(cgo[r]);
                float2 xif = unpack2(bif[r]);
                float2 xgo = unpack2(bgo[r]);
                float si = fsigm(rif.x + xif.x + nb_i);
                float sf = fsigm(rif.y + xif.y + nb_f);
                float tg = ftanh(rgo.x + xgo.x + nb_g);
                float so = fsigm(rgo.y + xgo.y + nb_o);
                float c  = sf * creg1[r] + si * tg;
                creg1[r] = c;
                hout1[rows[r] * HH + col] = so * ftanh(c);
            }
        }

        // ---- per-row-group barrier (16 CTAs per counter) ----
        if (tau < TT) {
            __syncthreads();                       // all reads + h stores done
            if (tid == 0) {
                __threadfence();                   // release h to GPU scope
                atomicAdd(barp, 1u);
            }
            // prefetch next interval's layer-0 pregates while peers arrive
            if (tau + 1 < TT) {
                #pragma unroll
                for (int r = 0; r < 4; r++) {
                    size_t base = ((size_t)rows[r] * TT + (tau + 1)) * GG + col;
                    pg_i[r] = g_GX[base];
                    pg_f[r] = g_GX[base + 256];
                    pg_g[r] = g_GX[base + 512];
                    pg_o[r] = g_GX[base + 768];
                }
            }
            if (tid == 0) {
                unsigned target = (unsigned)(tau + 1) * 16u;
                while (ld_acquire_u(barp) < target) { }
            }
            __syncthreads();
        }
    }
}

// ---------------- FC + log_softmax ------------------------------------------
__global__ void __launch_bounds__(128) fc_kernel(const float* __restrict__ wfc,
                                                 const float* __restrict__ bfc,
                                                 float* __restrict__ out) {
    const int b = blockIdx.x;
    const int tid = threadIdx.x;  // 128 = one class per thread
    __shared__ float h[256];
    // h1[511] written at tau=512 with parity (512-1)&1 = 1
    h[tid] = g_H1b[1][b * HH + tid];
    h[tid + 128] = g_H1b[1][b * HH + tid + 128];
    __syncthreads();

    float acc = bfc[tid];
    const float* wp = wfc + (size_t)tid * HH;
    #pragma unroll 8
    for (int k = 0; k < 256; k++) acc += h[k] * wp[k];

    float m = acc;
    #pragma unroll
    for (int o = 16; o > 0; o >>= 1)
        m = fmaxf(m, __shfl_xor_sync(0xffffffffu, m, o));
    __shared__ float smax[4], ssum[4];
    int wid = tid >> 5, lane = tid & 31;
    if (lane == 0) smax[wid] = m;
    __syncthreads();
    m = fmaxf(fmaxf(smax[0], smax[1]), fmaxf(smax[2], smax[3]));

    float e = expf(acc - m);
    float s = e;
    #pragma unroll
    for (int o = 16; o > 0; o >>= 1)
        s += __shfl_xor_sync(0xffffffffu, s, o);
    if (lane == 0) ssum[wid] = s;
    __syncthreads();
    s = ssum[0] + ssum[1] + ssum[2] + ssum[3];

    out[b * CC + tid] = acc - m - logf(s);
}

// ---------------- launch ------------------------------------------------------
extern "C" void kernel_launch(void* const* d_in, const int* in_sizes, int n_in,
                              void* d_out, int out_size) {
    const float* x    = (const float*)d_in[0];
    const float* wih0 = (const float*)d_in[1];
    const float* whh0 = (const float*)d_in[2];
    const float* bih0 = (const float*)d_in[3];
    const float* bhh0 = (const float*)d_in[4];
    const float* wih1 = (const float*)d_in[5];
    const float* whh1 = (const float*)d_in[6];
    const float* bih1 = (const float*)d_in[7];
    const float* bhh1 = (const float*)d_in[8];
    const float* wfc  = (const float*)d_in[9];
    const float* bfc  = (const float*)d_in[10];
    float* out = (float*)d_out;

    const int dual_smem = (3 * 256 * 64 + 32 * SA) * (int)sizeof(float); // 229888 B
    cudaFuncSetAttribute(lstm_dual,
                         cudaFuncAttributeMaxDynamicSharedMemorySize,
                         dual_smem);

    dim3 gemm_grid(16, 1024);   // N/64, M/128

    // 3 launches total: gemm0 -> lstm_dual (both layers pipelined) -> fc
    gemm_gx<<<gemm_grid, 256>>>(x, wih0, bih0, bhh0);
    lstm_dual<<<128, 128, dual_smem>>>(whh0, wih1, whh1, bih1, bhh1);
    fc_kernel<<<256, 128>>>(wfc, bfc, out);
}